// round 5
// baseline (speedup 1.0000x reference)
#include <cuda_runtime.h>
#include <cuda_bf16.h>
#include <cstdint>

#define NB 64
#define NM 512
#define ND 2048
#define NK 32

// ---- scratch (device globals: allocation-free) ----
__device__ __align__(256) __nv_bfloat16 g_xraw[(size_t)NB*NM*ND];  // bf16 x copy
__device__ __align__(256) __nv_bfloat16 g_sap[NB*NM*NK];           // sa * rnorm
__device__ float g_S[NB*NK];
__device__ float g_nsq[NB*NK];
__device__ int   g_cnt[NB];

__device__ __forceinline__ void mma_bf16(float c[4],
    unsigned a0, unsigned a1, unsigned a2, unsigned a3,
    unsigned b0, unsigned b1) {
  asm volatile(
    "mma.sync.aligned.m16n8k16.row.col.f32.bf16.bf16.f32 "
    "{%0,%1,%2,%3}, {%4,%5,%6,%7}, {%8,%9}, {%0,%1,%2,%3};\n"
    : "+f"(c[0]), "+f"(c[1]), "+f"(c[2]), "+f"(c[3])
    : "r"(a0), "r"(a1), "r"(a2), "r"(a3), "r"(b0), "r"(b1));
}
__device__ __forceinline__ void cp16(void* dst, const void* src) {
  unsigned d = (unsigned)__cvta_generic_to_shared(dst);
  asm volatile("cp.async.cg.shared.global [%0], [%1], 16;\n" :: "r"(d), "l"(src));
}
__device__ __forceinline__ void cp_commit() { asm volatile("cp.async.commit_group;\n"); }
__device__ __forceinline__ void cp_wait1()  { asm volatile("cp.async.wait_group 1;\n"); }

// ================= KZ: zero accumulators =================
__global__ void kz_kernel() {
  int tid = threadIdx.x;
  for (int i = tid; i < NB * NK; i += 256) { g_S[i] = 0.f; g_nsq[i] = 0.f; }
  if (tid < NB) g_cnt[tid] = 0;
}

// ================= KA: norm + logits + softmax (R2 version, verbatim) =====
#define KA_XS 72   // fp32 smem row stride (floats)
#define KA_WS 72   // bf16 smem row stride (halves)
#define KA_XBYTES (2*64*KA_XS*4)           // 36864
#define KA_WBYTES (2*32*KA_WS*2)           // 9216
__global__ __launch_bounds__(256) void ka_kernel(const float* __restrict__ x,
                                                 const float* __restrict__ Wm) {
  __shared__ __align__(16) char blob[KA_XBYTES + KA_WBYTES];
  float* xf = reinterpret_cast<float*>(blob);                 // [2][64][72]
  __nv_bfloat16* wb = reinterpret_cast<__nv_bfloat16*>(blob + KA_XBYTES); // [2][32][72]
  float (*slog)[36] = reinterpret_cast<float(*)[36]>(blob);   // alias (post-loop only)
  __shared__ float srn[64];

  const int tid = threadIdx.x, lane = tid & 31, w = tid >> 5;
  const int g = lane >> 2, q = lane & 3;
  const int r0 = blockIdx.x * 64;
  const int mt = w & 3, nbase = (w >> 2) * 16;

  float ssq = 0.f;
  float c[2][4];
#pragma unroll
  for (int i = 0; i < 2; i++) { c[i][0]=c[i][1]=c[i][2]=c[i][3]=0.f; }

  const int crow = tid >> 2, cseg = (tid & 3) * 16;   // convert-phase assignment
  const int wrw = tid >> 3, wcw = (tid & 7) * 8;      // W-load assignment

  // prologue: chunk 0
  {
#pragma unroll
    for (int j = 0; j < 4; j++) {
      int op = tid + 256 * j;
      int row = op >> 4, seg = op & 15;
      cp16(xf + row * KA_XS + seg * 4,
           x + (size_t)(r0 + row) * ND + seg * 4);
    }
    cp_commit();
    float4 wv0 = *reinterpret_cast<const float4*>(Wm + (size_t)wrw * ND + wcw);
    float4 wv1 = *reinterpret_cast<const float4*>(Wm + (size_t)wrw * ND + wcw + 4);
    __nv_bfloat162 h0 = __float22bfloat162_rn(make_float2(wv0.x, wv0.y));
    __nv_bfloat162 h1 = __float22bfloat162_rn(make_float2(wv0.z, wv0.w));
    __nv_bfloat162 h2 = __float22bfloat162_rn(make_float2(wv1.x, wv1.y));
    __nv_bfloat162 h3 = __float22bfloat162_rn(make_float2(wv1.z, wv1.w));
    uint4 pk;
    pk.x = *reinterpret_cast<unsigned*>(&h0); pk.y = *reinterpret_cast<unsigned*>(&h1);
    pk.z = *reinterpret_cast<unsigned*>(&h2); pk.w = *reinterpret_cast<unsigned*>(&h3);
    *reinterpret_cast<uint4*>(wb + wrw * KA_WS + wcw) = pk;
  }

  for (int it = 0; it < 32; it++) {
    const int buf = it & 1, nbuf = buf ^ 1;
    float4 wv0, wv1;
    const bool more = (it + 1 < 32);
    if (more) {
      const int c1 = (it + 1) * 64;
#pragma unroll
      for (int j = 0; j < 4; j++) {
        int op = tid + 256 * j;
        int row = op >> 4, seg = op & 15;
        cp16(xf + nbuf * (64 * KA_XS) + row * KA_XS + seg * 4,
             x + (size_t)(r0 + row) * ND + c1 + seg * 4);
      }
      wv0 = *reinterpret_cast<const float4*>(Wm + (size_t)wrw * ND + c1 + wcw);
      wv1 = *reinterpret_cast<const float4*>(Wm + (size_t)wrw * ND + c1 + wcw + 4);
    }
    cp_commit();
    cp_wait1();
    __syncthreads();

    const float* xb = xf + buf * (64 * KA_XS);
    const __nv_bfloat16* wbb = wb + buf * (32 * KA_WS);

    // convert + sumsq + bf16 global store
    {
      const float* src = xb + crow * KA_XS + cseg;
      float4 v0 = *reinterpret_cast<const float4*>(src);
      float4 v1 = *reinterpret_cast<const float4*>(src + 4);
      float4 v2 = *reinterpret_cast<const float4*>(src + 8);
      float4 v3 = *reinterpret_cast<const float4*>(src + 12);
      ssq += v0.x*v0.x + v0.y*v0.y + v0.z*v0.z + v0.w*v0.w
           + v1.x*v1.x + v1.y*v1.y + v1.z*v1.z + v1.w*v1.w
           + v2.x*v2.x + v2.y*v2.y + v2.z*v2.z + v2.w*v2.w
           + v3.x*v3.x + v3.y*v3.y + v3.z*v3.z + v3.w*v3.w;
      __nv_bfloat162 p0 = __float22bfloat162_rn(make_float2(v0.x, v0.y));
      __nv_bfloat162 p1 = __float22bfloat162_rn(make_float2(v0.z, v0.w));
      __nv_bfloat162 p2 = __float22bfloat162_rn(make_float2(v1.x, v1.y));
      __nv_bfloat162 p3 = __float22bfloat162_rn(make_float2(v1.z, v1.w));
      __nv_bfloat162 p4 = __float22bfloat162_rn(make_float2(v2.x, v2.y));
      __nv_bfloat162 p5 = __float22bfloat162_rn(make_float2(v2.z, v2.w));
      __nv_bfloat162 p6 = __float22bfloat162_rn(make_float2(v3.x, v3.y));
      __nv_bfloat162 p7 = __float22bfloat162_rn(make_float2(v3.z, v3.w));
      uint4 o0, o1;
      o0.x = *reinterpret_cast<unsigned*>(&p0); o0.y = *reinterpret_cast<unsigned*>(&p1);
      o0.z = *reinterpret_cast<unsigned*>(&p2); o0.w = *reinterpret_cast<unsigned*>(&p3);
      o1.x = *reinterpret_cast<unsigned*>(&p4); o1.y = *reinterpret_cast<unsigned*>(&p5);
      o1.z = *reinterpret_cast<unsigned*>(&p6); o1.w = *reinterpret_cast<unsigned*>(&p7);
      __nv_bfloat16* dst = g_xraw + (size_t)(r0 + crow) * ND + it * 64 + cseg;
      *reinterpret_cast<uint4*>(dst)     = o0;
      *reinterpret_cast<uint4*>(dst + 8) = o1;
    }

    // mma over this chunk: 4 k-steps of 16
#pragma unroll
    for (int ks = 0; ks < 4; ks++) {
      const int k0 = ks * 16;
      const int rl = 16 * mt + g;
      float2 pa = *reinterpret_cast<const float2*>(xb + rl * KA_XS + k0 + 2*q);
      float2 pb = *reinterpret_cast<const float2*>(xb + (rl+8) * KA_XS + k0 + 2*q);
      float2 pc = *reinterpret_cast<const float2*>(xb + rl * KA_XS + k0 + 2*q + 8);
      float2 pd = *reinterpret_cast<const float2*>(xb + (rl+8) * KA_XS + k0 + 2*q + 8);
      __nv_bfloat162 ha = __float22bfloat162_rn(pa);
      __nv_bfloat162 hb = __float22bfloat162_rn(pb);
      __nv_bfloat162 hc = __float22bfloat162_rn(pc);
      __nv_bfloat162 hd = __float22bfloat162_rn(pd);
      unsigned a0 = *reinterpret_cast<unsigned*>(&ha);
      unsigned a1 = *reinterpret_cast<unsigned*>(&hb);
      unsigned a2 = *reinterpret_cast<unsigned*>(&hc);
      unsigned a3 = *reinterpret_cast<unsigned*>(&hd);
#pragma unroll
      for (int nt = 0; nt < 2; nt++) {
        unsigned b0 = *reinterpret_cast<const unsigned*>(
            wbb + (nbase + 8*nt + g) * KA_WS + k0 + 2*q);
        unsigned b1 = *reinterpret_cast<const unsigned*>(
            wbb + (nbase + 8*nt + g) * KA_WS + k0 + 2*q + 8);
        mma_bf16(c[nt], a0, a1, a2, a3, b0, b1);
      }
    }

    if (more) {
      __nv_bfloat162 h0 = __float22bfloat162_rn(make_float2(wv0.x, wv0.y));
      __nv_bfloat162 h1 = __float22bfloat162_rn(make_float2(wv0.z, wv0.w));
      __nv_bfloat162 h2 = __float22bfloat162_rn(make_float2(wv1.x, wv1.y));
      __nv_bfloat162 h3 = __float22bfloat162_rn(make_float2(wv1.z, wv1.w));
      uint4 pk;
      pk.x = *reinterpret_cast<unsigned*>(&h0); pk.y = *reinterpret_cast<unsigned*>(&h1);
      pk.z = *reinterpret_cast<unsigned*>(&h2); pk.w = *reinterpret_cast<unsigned*>(&h3);
      *reinterpret_cast<uint4*>(wb + nbuf * (32 * KA_WS) + wrw * KA_WS + wcw) = pk;
    }
    __syncthreads();
  }

  // row norms
  ssq += __shfl_xor_sync(0xffffffffu, ssq, 1);
  ssq += __shfl_xor_sync(0xffffffffu, ssq, 2);
  if ((tid & 3) == 0) srn[crow] = rsqrtf(fmaxf(ssq, 1e-24f));

#pragma unroll
  for (int nt = 0; nt < 2; nt++) {
    slog[16*mt + g    ][nbase + 8*nt + 2*q]     = c[nt][0];
    slog[16*mt + g    ][nbase + 8*nt + 2*q + 1] = c[nt][1];
    slog[16*mt + g + 8][nbase + 8*nt + 2*q]     = c[nt][2];
    slog[16*mt + g + 8][nbase + 8*nt + 2*q + 1] = c[nt][3];
  }
  __syncthreads();

  if (tid < 64) {
    float rn = srn[tid];
    float l[NK];
    float mx = -1e30f;
#pragma unroll
    for (int k = 0; k < NK; k++) { l[k] = slog[tid][k] * rn; mx = fmaxf(mx, l[k]); }
    float s = 0.f;
#pragma unroll
    for (int k = 0; k < NK; k++) { l[k] = expf(l[k] - mx); s += l[k]; }
    float inv = 1.f / s;
#pragma unroll
    for (int k = 0; k < NK; k++) l[k] *= inv;
#pragma unroll
    for (int k = 0; k < NK; k += 8) {
      __nv_bfloat162 q0 = __float22bfloat162_rn(make_float2(l[k]*rn,   l[k+1]*rn));
      __nv_bfloat162 q1 = __float22bfloat162_rn(make_float2(l[k+2]*rn, l[k+3]*rn));
      __nv_bfloat162 q2 = __float22bfloat162_rn(make_float2(l[k+4]*rn, l[k+5]*rn));
      __nv_bfloat162 q3 = __float22bfloat162_rn(make_float2(l[k+6]*rn, l[k+7]*rn));
      uint4 pk;
      pk.x = *reinterpret_cast<unsigned*>(&q0); pk.y = *reinterpret_cast<unsigned*>(&q1);
      pk.z = *reinterpret_cast<unsigned*>(&q2); pk.w = *reinterpret_cast<unsigned*>(&q3);
      *reinterpret_cast<uint4*>(&g_sap[(size_t)(r0 + tid) * NK + k]) = pk;
    }
#pragma unroll
    for (int k = 0; k < NK; k++) slog[tid][k] = l[k];
  }
  __syncthreads();

  if (tid < NK) {
    float s = 0.f;
#pragma unroll
    for (int r = 0; r < 64; r++) s += slog[r][tid];
    atomicAdd(&g_S[(r0 / NM) * NK + tid], s);
  }
}

// ================= KB2: agg GEMM + normalize + direct output =============
// grid 128: CTA = (batch b, d-half h). 4 d-chunks of 256, pre-norm vlad kept
// in smem; cross-pair nsq exchange via global atomics + spin (single wave).
#define KB_SBS 264           // x tile stride (halves)
#define KB_SAT 520           // persistent sa'^T stride (halves)
#define OFFB_SB  0                           // [2][32][264] bf16 = 33792
#define OFFB_SAT 33792                       // [32][520] bf16    = 33280
#define OFFB_VAC 67072                       // [32][1032] f32    = 132096
#define OFFB_NSQ 199168                      // [32] f32
#define OFFB_SCL 199296                      // [32] f32
#define OFFB_SS  199424                      // [32] f32
#define KB_SMEM  199680
__global__ __launch_bounds__(256) void kb2_kernel(const float* __restrict__ cent,
                                                  float* __restrict__ out) {
  extern __shared__ __align__(16) char kbb[];
  __nv_bfloat16* sB  = reinterpret_cast<__nv_bfloat16*>(kbb + OFFB_SB);
  __nv_bfloat16* sAt = reinterpret_cast<__nv_bfloat16*>(kbb + OFFB_SAT);
  float* vac  = reinterpret_cast<float*>(kbb + OFFB_VAC);   // [32][1032]
  float* snsq = reinterpret_cast<float*>(kbb + OFFB_NSQ);
  float* sscl = reinterpret_cast<float*>(kbb + OFFB_SCL);
  float* sS   = reinterpret_cast<float*>(kbb + OFFB_SS);

  const int tid = threadIdx.x, lane = tid & 31, w = tid >> 5;
  const int g = lane >> 2, q = lane & 3;
  const int b = blockIdx.x >> 1, h = blockIdx.x & 1;
  const int mt = w & 1, nbase = (w >> 1) * 64;
  const int rl = 16 * mt + g, rh = rl + 8;

  if (tid < NK) { sS[tid] = g_S[b * NK + tid]; snsq[tid] = 0.f; }

  const __nv_bfloat16* xb = g_xraw + (size_t)b * NM * ND + h * 1024;
  const __nv_bfloat16* ab = g_sap + (size_t)b * NM * NK;

  // persistent sa'^T [32 k][512 m]: 8 uint4 loads per thread, scatter
#pragma unroll
  for (int j = 0; j < 8; j++) {
    int u = tid + 256 * j;           // 0..2047
    int m = u >> 2, seg = u & 3;
    uint4 pk = *reinterpret_cast<const uint4*>(ab + m * NK + seg * 8);
    const __nv_bfloat16* hp = reinterpret_cast<const __nv_bfloat16*>(&pk);
#pragma unroll
    for (int jj = 0; jj < 8; jj++) sAt[(seg * 8 + jj) * KB_SAT + m] = hp[jj];
  }
  __syncthreads();

  float sql = 0.f, sqh = 0.f;

  for (int dc = 0; dc < 4; dc++) {
    const int dloc = dc * 256;            // local col base within half
    float c[8][4];
#pragma unroll
    for (int i = 0; i < 8; i++) { c[i][0]=c[i][1]=c[i][2]=c[i][3]=0.f; }

    // prologue: stage 0 (32 m rows x 256 cols)
#pragma unroll
    for (int j = 0; j < 4; j++) {
      int op = tid + 256 * j;
      int row = op >> 5, seg = (op & 31) * 8;
      cp16(sB + row * KB_SBS + seg, xb + (size_t)row * ND + dloc + seg);
    }
    cp_commit();

    for (int it = 0; it < 16; it++) {
      const int buf = it & 1, nbuf = buf ^ 1;
      const bool more = (it + 1 < 16);
      if (more) {
        const int m0 = (it + 1) * 32;
#pragma unroll
        for (int j = 0; j < 4; j++) {
          int op = tid + 256 * j;
          int row = op >> 5, seg = (op & 31) * 8;
          cp16(sB + nbuf * (32 * KB_SBS) + row * KB_SBS + seg,
               xb + (size_t)(m0 + row) * ND + dloc + seg);
        }
      }
      cp_commit();
      cp_wait1();
      __syncthreads();

      const __nv_bfloat16* sBb = sB + buf * (32 * KB_SBS);
      const int mbase = it * 32;
#pragma unroll
      for (int ks = 0; ks < 2; ks++) {
        const int k0 = ks * 16;
        unsigned a0 = *reinterpret_cast<const unsigned*>(sAt + rl * KB_SAT + mbase + k0 + 2*q);
        unsigned a1 = *reinterpret_cast<const unsigned*>(sAt + rh * KB_SAT + mbase + k0 + 2*q);
        unsigned a2 = *reinterpret_cast<const unsigned*>(sAt + rl * KB_SAT + mbase + k0 + 2*q + 8);
        unsigned a3 = *reinterpret_cast<const unsigned*>(sAt + rh * KB_SAT + mbase + k0 + 2*q + 8);
#pragma unroll
        for (int nt = 0; nt < 8; nt++) {
          unsigned b0, b1;
          unsigned addr = (unsigned)__cvta_generic_to_shared(
              sBb + (k0 + (lane & 15)) * KB_SBS + nbase + 8 * nt);
          asm volatile(
              "ldmatrix.sync.aligned.m8n8.x2.trans.shared.b16 {%0,%1}, [%2];\n"
              : "=r"(b0), "=r"(b1) : "r"(addr));
          mma_bf16(c[nt], a0, a1, a2, a3, b0, b1);
        }
      }
      __syncthreads();
    }

    // epilogue for this d-chunk: subtract S*cent, sumsq, stash in smem vac
    const float Sl = sS[rl], Sh = sS[rh];
#pragma unroll
    for (int nt = 0; nt < 8; nt++) {
      const int cl_ = nbase + 8 * nt + 2 * q;        // 0..255 within chunk
      const int gcol = h * 1024 + dloc + cl_;        // global d col
      float2 cl = *reinterpret_cast<const float2*>(cent + (size_t)rl * ND + gcol);
      float2 ch = *reinterpret_cast<const float2*>(cent + (size_t)rh * ND + gcol);
      float v0 = c[nt][0] - Sl * cl.x, v1 = c[nt][1] - Sl * cl.y;
      float v2 = c[nt][2] - Sh * ch.x, v3 = c[nt][3] - Sh * ch.y;
      sql += v0 * v0 + v1 * v1;
      sqh += v2 * v2 + v3 * v3;
      float2 o0; o0.x = v0; o0.y = v1;
      float2 o1; o1.x = v2; o1.y = v3;
      *reinterpret_cast<float2*>(vac + rl * 1032 + dloc + cl_) = o0;
      *reinterpret_cast<float2*>(vac + rh * 1032 + dloc + cl_) = o1;
    }
  }

  // reduce sumsq within quads, accumulate into smem then global
  sql += __shfl_xor_sync(0xffffffffu, sql, 1);
  sql += __shfl_xor_sync(0xffffffffu, sql, 2);
  sqh += __shfl_xor_sync(0xffffffffu, sqh, 1);
  sqh += __shfl_xor_sync(0xffffffffu, sqh, 2);
  if (q == 0) { atomicAdd(&snsq[rl], sql); atomicAdd(&snsq[rh], sqh); }
  __syncthreads();

  if (tid < NK) atomicAdd(&g_nsq[b * NK + tid], snsq[tid]);
  __threadfence();
  __syncthreads();
  if (tid == 0) {
    atomicAdd(&g_cnt[b], 1);
    while (*reinterpret_cast<volatile int*>(&g_cnt[b]) < 2) { }
  }
  __syncthreads();
  __threadfence();
  if (tid < NK) {
    float tot = atomicAdd(&g_nsq[b * NK + tid], 0.0f);
    sscl[tid] = rsqrtf(fmaxf(tot, 1e-24f) * 32.0f);   // incl final sqrt(K)
  }
  __syncthreads();

  // write output: 32 rows x 1024 cols, coalesced float4
  float* ob = out + (size_t)b * (NK * ND) + h * 1024;
#pragma unroll
  for (int r = 0; r < NK; r++) {
    float sc = sscl[r];
    float4 v = *reinterpret_cast<const float4*>(vac + r * 1032 + tid * 4);
    v.x *= sc; v.y *= sc; v.z *= sc; v.w *= sc;
    *reinterpret_cast<float4*>(ob + (size_t)r * ND + tid * 4) = v;
  }
}

extern "C" void kernel_launch(void* const* d_in, const int* in_sizes, int n_in,
                              void* d_out, int out_size) {
  const float* x    = (const float*)d_in[0];
  const float* Wm   = (const float*)d_in[1];
  const float* cent = (const float*)d_in[2];
  float* out = (float*)d_out;

  static bool attr_set = false;
  if (!attr_set) {
    cudaFuncSetAttribute(kb2_kernel,
                         cudaFuncAttributeMaxDynamicSharedMemorySize, KB_SMEM);
    attr_set = true;
  }

  kz_kernel<<<1, 256>>>();
  ka_kernel<<<(NB * NM) / 64, 256>>>(x, Wm);
  kb2_kernel<<<NB * 2, 256, KB_SMEM>>>(cent, out);
}

// round 10
// speedup vs baseline: 1.1373x; 1.1373x over previous
#include <cuda_runtime.h>
#include <cuda_bf16.h>
#include <cstdint>

#define NB 64
#define NM 512
#define ND 2048
#define NK 32

// ---- scratch (device globals: allocation-free) ----
__device__ __align__(256) __nv_bfloat16 g_xraw[(size_t)NB*NM*ND];  // bf16 x copy
__device__ __align__(256) __nv_bfloat16 g_sap[NB*NM*NK];           // sa * rnorm
__device__ float g_S[NB*NK];
__device__ float g_nsq[NB*NK];
__device__ int   g_cnt[NB];

__device__ __forceinline__ void mma_bf16(float c[4],
    unsigned a0, unsigned a1, unsigned a2, unsigned a3,
    unsigned b0, unsigned b1) {
  asm volatile(
    "mma.sync.aligned.m16n8k16.row.col.f32.bf16.bf16.f32 "
    "{%0,%1,%2,%3}, {%4,%5,%6,%7}, {%8,%9}, {%0,%1,%2,%3};\n"
    : "+f"(c[0]), "+f"(c[1]), "+f"(c[2]), "+f"(c[3])
    : "r"(a0), "r"(a1), "r"(a2), "r"(a3), "r"(b0), "r"(b1));
}
__device__ __forceinline__ void cp16(void* dst, const void* src) {
  unsigned d = (unsigned)__cvta_generic_to_shared(dst);
  asm volatile("cp.async.cg.shared.global [%0], [%1], 16;\n" :: "r"(d), "l"(src));
}
__device__ __forceinline__ void cp_commit() { asm volatile("cp.async.commit_group;\n"); }
__device__ __forceinline__ void cp_wait1()  { asm volatile("cp.async.wait_group 1;\n"); }

// ================= KZ: zero accumulators =================
__global__ void kz_kernel() {
  int i = blockIdx.x * blockDim.x + threadIdx.x;
  if (i < NB * NK) { g_S[i] = 0.f; g_nsq[i] = 0.f; }
  if (i < NB) g_cnt[i] = 0;
}

// ================= KA: norm + logits + softmax (R2 version, verbatim) =====
#define KA_XS 72   // fp32 smem row stride (floats)
#define KA_WS 72   // bf16 smem row stride (halves)
#define KA_XBYTES (2*64*KA_XS*4)           // 36864
#define KA_WBYTES (2*32*KA_WS*2)           // 9216
__global__ __launch_bounds__(256) void ka_kernel(const float* __restrict__ x,
                                                 const float* __restrict__ Wm) {
  __shared__ __align__(16) char blob[KA_XBYTES + KA_WBYTES];
  float* xf = reinterpret_cast<float*>(blob);                 // [2][64][72]
  __nv_bfloat16* wb = reinterpret_cast<__nv_bfloat16*>(blob + KA_XBYTES); // [2][32][72]
  float (*slog)[36] = reinterpret_cast<float(*)[36]>(blob);   // alias (post-loop only)
  __shared__ float srn[64];

  const int tid = threadIdx.x, lane = tid & 31, w = tid >> 5;
  const int g = lane >> 2, q = lane & 3;
  const int r0 = blockIdx.x * 64;
  const int mt = w & 3, nbase = (w >> 2) * 16;

  float ssq = 0.f;
  float c[2][4];
#pragma unroll
  for (int i = 0; i < 2; i++) { c[i][0]=c[i][1]=c[i][2]=c[i][3]=0.f; }

  const int crow = tid >> 2, cseg = (tid & 3) * 16;   // convert-phase assignment
  const int wrw = tid >> 3, wcw = (tid & 7) * 8;      // W-load assignment

  // prologue: chunk 0
  {
#pragma unroll
    for (int j = 0; j < 4; j++) {
      int op = tid + 256 * j;
      int row = op >> 4, seg = op & 15;
      cp16(xf + row * KA_XS + seg * 4,
           x + (size_t)(r0 + row) * ND + seg * 4);
    }
    cp_commit();
    float4 wv0 = *reinterpret_cast<const float4*>(Wm + (size_t)wrw * ND + wcw);
    float4 wv1 = *reinterpret_cast<const float4*>(Wm + (size_t)wrw * ND + wcw + 4);
    __nv_bfloat162 h0 = __float22bfloat162_rn(make_float2(wv0.x, wv0.y));
    __nv_bfloat162 h1 = __float22bfloat162_rn(make_float2(wv0.z, wv0.w));
    __nv_bfloat162 h2 = __float22bfloat162_rn(make_float2(wv1.x, wv1.y));
    __nv_bfloat162 h3 = __float22bfloat162_rn(make_float2(wv1.z, wv1.w));
    uint4 pk;
    pk.x = *reinterpret_cast<unsigned*>(&h0); pk.y = *reinterpret_cast<unsigned*>(&h1);
    pk.z = *reinterpret_cast<unsigned*>(&h2); pk.w = *reinterpret_cast<unsigned*>(&h3);
    *reinterpret_cast<uint4*>(wb + wrw * KA_WS + wcw) = pk;
  }

  for (int it = 0; it < 32; it++) {
    const int buf = it & 1, nbuf = buf ^ 1;
    float4 wv0, wv1;
    const bool more = (it + 1 < 32);
    if (more) {
      const int c1 = (it + 1) * 64;
#pragma unroll
      for (int j = 0; j < 4; j++) {
        int op = tid + 256 * j;
        int row = op >> 4, seg = op & 15;
        cp16(xf + nbuf * (64 * KA_XS) + row * KA_XS + seg * 4,
             x + (size_t)(r0 + row) * ND + c1 + seg * 4);
      }
      wv0 = *reinterpret_cast<const float4*>(Wm + (size_t)wrw * ND + c1 + wcw);
      wv1 = *reinterpret_cast<const float4*>(Wm + (size_t)wrw * ND + c1 + wcw + 4);
    }
    cp_commit();
    cp_wait1();
    __syncthreads();

    const float* xb = xf + buf * (64 * KA_XS);
    const __nv_bfloat16* wbb = wb + buf * (32 * KA_WS);

    // convert + sumsq + bf16 global store
    {
      const float* src = xb + crow * KA_XS + cseg;
      float4 v0 = *reinterpret_cast<const float4*>(src);
      float4 v1 = *reinterpret_cast<const float4*>(src + 4);
      float4 v2 = *reinterpret_cast<const float4*>(src + 8);
      float4 v3 = *reinterpret_cast<const float4*>(src + 12);
      ssq += v0.x*v0.x + v0.y*v0.y + v0.z*v0.z + v0.w*v0.w
           + v1.x*v1.x + v1.y*v1.y + v1.z*v1.z + v1.w*v1.w
           + v2.x*v2.x + v2.y*v2.y + v2.z*v2.z + v2.w*v2.w
           + v3.x*v3.x + v3.y*v3.y + v3.z*v3.z + v3.w*v3.w;
      __nv_bfloat162 p0 = __float22bfloat162_rn(make_float2(v0.x, v0.y));
      __nv_bfloat162 p1 = __float22bfloat162_rn(make_float2(v0.z, v0.w));
      __nv_bfloat162 p2 = __float22bfloat162_rn(make_float2(v1.x, v1.y));
      __nv_bfloat162 p3 = __float22bfloat162_rn(make_float2(v1.z, v1.w));
      __nv_bfloat162 p4 = __float22bfloat162_rn(make_float2(v2.x, v2.y));
      __nv_bfloat162 p5 = __float22bfloat162_rn(make_float2(v2.z, v2.w));
      __nv_bfloat162 p6 = __float22bfloat162_rn(make_float2(v3.x, v3.y));
      __nv_bfloat162 p7 = __float22bfloat162_rn(make_float2(v3.z, v3.w));
      uint4 o0, o1;
      o0.x = *reinterpret_cast<unsigned*>(&p0); o0.y = *reinterpret_cast<unsigned*>(&p1);
      o0.z = *reinterpret_cast<unsigned*>(&p2); o0.w = *reinterpret_cast<unsigned*>(&p3);
      o1.x = *reinterpret_cast<unsigned*>(&p4); o1.y = *reinterpret_cast<unsigned*>(&p5);
      o1.z = *reinterpret_cast<unsigned*>(&p6); o1.w = *reinterpret_cast<unsigned*>(&p7);
      __nv_bfloat16* dst = g_xraw + (size_t)(r0 + crow) * ND + it * 64 + cseg;
      *reinterpret_cast<uint4*>(dst)     = o0;
      *reinterpret_cast<uint4*>(dst + 8) = o1;
    }

    // mma over this chunk: 4 k-steps of 16
#pragma unroll
    for (int ks = 0; ks < 4; ks++) {
      const int k0 = ks * 16;
      const int rl = 16 * mt + g;
      float2 pa = *reinterpret_cast<const float2*>(xb + rl * KA_XS + k0 + 2*q);
      float2 pb = *reinterpret_cast<const float2*>(xb + (rl+8) * KA_XS + k0 + 2*q);
      float2 pc = *reinterpret_cast<const float2*>(xb + rl * KA_XS + k0 + 2*q + 8);
      float2 pd = *reinterpret_cast<const float2*>(xb + (rl+8) * KA_XS + k0 + 2*q + 8);
      __nv_bfloat162 ha = __float22bfloat162_rn(pa);
      __nv_bfloat162 hb = __float22bfloat162_rn(pb);
      __nv_bfloat162 hc = __float22bfloat162_rn(pc);
      __nv_bfloat162 hd = __float22bfloat162_rn(pd);
      unsigned a0 = *reinterpret_cast<unsigned*>(&ha);
      unsigned a1 = *reinterpret_cast<unsigned*>(&hb);
      unsigned a2 = *reinterpret_cast<unsigned*>(&hc);
      unsigned a3 = *reinterpret_cast<unsigned*>(&hd);
#pragma unroll
      for (int nt = 0; nt < 2; nt++) {
        unsigned b0 = *reinterpret_cast<const unsigned*>(
            wbb + (nbase + 8*nt + g) * KA_WS + k0 + 2*q);
        unsigned b1 = *reinterpret_cast<const unsigned*>(
            wbb + (nbase + 8*nt + g) * KA_WS + k0 + 2*q + 8);
        mma_bf16(c[nt], a0, a1, a2, a3, b0, b1);
      }
    }

    if (more) {
      __nv_bfloat162 h0 = __float22bfloat162_rn(make_float2(wv0.x, wv0.y));
      __nv_bfloat162 h1 = __float22bfloat162_rn(make_float2(wv0.z, wv0.w));
      __nv_bfloat162 h2 = __float22bfloat162_rn(make_float2(wv1.x, wv1.y));
      __nv_bfloat162 h3 = __float22bfloat162_rn(make_float2(wv1.z, wv1.w));
      uint4 pk;
      pk.x = *reinterpret_cast<unsigned*>(&h0); pk.y = *reinterpret_cast<unsigned*>(&h1);
      pk.z = *reinterpret_cast<unsigned*>(&h2); pk.w = *reinterpret_cast<unsigned*>(&h3);
      *reinterpret_cast<uint4*>(wb + nbuf * (32 * KA_WS) + wrw * KA_WS + wcw) = pk;
    }
    __syncthreads();
  }

  // row norms
  ssq += __shfl_xor_sync(0xffffffffu, ssq, 1);
  ssq += __shfl_xor_sync(0xffffffffu, ssq, 2);
  if ((tid & 3) == 0) srn[crow] = rsqrtf(fmaxf(ssq, 1e-24f));

#pragma unroll
  for (int nt = 0; nt < 2; nt++) {
    slog[16*mt + g    ][nbase + 8*nt + 2*q]     = c[nt][0];
    slog[16*mt + g    ][nbase + 8*nt + 2*q + 1] = c[nt][1];
    slog[16*mt + g + 8][nbase + 8*nt + 2*q]     = c[nt][2];
    slog[16*mt + g + 8][nbase + 8*nt + 2*q + 1] = c[nt][3];
  }
  __syncthreads();

  if (tid < 64) {
    float rn = srn[tid];
    float l[NK];
    float mx = -1e30f;
#pragma unroll
    for (int k = 0; k < NK; k++) { l[k] = slog[tid][k] * rn; mx = fmaxf(mx, l[k]); }
    float s = 0.f;
#pragma unroll
    for (int k = 0; k < NK; k++) { l[k] = expf(l[k] - mx); s += l[k]; }
    float inv = 1.f / s;
#pragma unroll
    for (int k = 0; k < NK; k++) l[k] *= inv;
#pragma unroll
    for (int k = 0; k < NK; k += 8) {
      __nv_bfloat162 q0 = __float22bfloat162_rn(make_float2(l[k]*rn,   l[k+1]*rn));
      __nv_bfloat162 q1 = __float22bfloat162_rn(make_float2(l[k+2]*rn, l[k+3]*rn));
      __nv_bfloat162 q2 = __float22bfloat162_rn(make_float2(l[k+4]*rn, l[k+5]*rn));
      __nv_bfloat162 q3 = __float22bfloat162_rn(make_float2(l[k+6]*rn, l[k+7]*rn));
      uint4 pk;
      pk.x = *reinterpret_cast<unsigned*>(&q0); pk.y = *reinterpret_cast<unsigned*>(&q1);
      pk.z = *reinterpret_cast<unsigned*>(&q2); pk.w = *reinterpret_cast<unsigned*>(&q3);
      *reinterpret_cast<uint4*>(&g_sap[(size_t)(r0 + tid) * NK + k]) = pk;
    }
#pragma unroll
    for (int k = 0; k < NK; k++) slog[tid][k] = l[k];
  }
  __syncthreads();

  if (tid < NK) {
    float s = 0.f;
#pragma unroll
    for (int r = 0; r < 64; r++) s += slog[r][tid];
    atomicAdd(&g_S[(r0 / NM) * NK + tid], s);
  }
}

// ================= KB2: R2 agg GEMM + fused normalize/output ==============
// grid 512 (8 CTAs per batch), 39KB smem, launch_bounds(256,4) => regs<=64 =>
// occupancy >=4/SM => 592 slots >= 512 CTAs => single wave. Spin is bounded
// with nanosleep so a residency-model failure degrades instead of hanging.
#define KB_SBS 264   // x tile stride (halves)
#define KB_SAS 40    // sa'^T tile stride (halves)
__global__ __launch_bounds__(256, 4) void kb2_kernel(const float* __restrict__ cent,
                                                     float* __restrict__ out) {
  __shared__ __align__(16) __nv_bfloat16 sB[2][32][KB_SBS];
  __shared__ __align__(16) __nv_bfloat16 sA[2][NK][KB_SAS];
  __shared__ float sS[NK], snsq[NK], sscl[NK];

  const int tid = threadIdx.x, lane = tid & 31, w = tid >> 5;
  const int g = lane >> 2, q = lane & 3;
  const int b  = blockIdx.x >> 3;
  const int d0 = (blockIdx.x & 7) * 256;
  if (tid < NK) { sS[tid] = g_S[b * NK + tid]; snsq[tid] = 0.f; }

  const int mt = w & 1, nbase = (w >> 1) * 64;
  const int arow = tid >> 2, aseg = tid & 3;   // sa' load assignment (tid<128)
  float c[8][4];
#pragma unroll
  for (int i = 0; i < 8; i++) { c[i][0]=c[i][1]=c[i][2]=c[i][3]=0.f; }

  // prologue: stage 0
  {
#pragma unroll
    for (int j = 0; j < 4; j++) {
      int op = tid + 256 * j;
      int row = op >> 5, seg = op & 31;
      cp16(&sB[0][row][seg * 8],
           g_xraw + (size_t)(b * NM + row) * ND + d0 + seg * 8);
    }
    cp_commit();
    if (tid < 128) {
      uint4 pk = *reinterpret_cast<const uint4*>(
          &g_sap[(size_t)(b * NM + arow) * NK + aseg * 8]);
      const __nv_bfloat16* hp = reinterpret_cast<const __nv_bfloat16*>(&pk);
#pragma unroll
      for (int jj = 0; jj < 8; jj++) sA[0][aseg * 8 + jj][arow] = hp[jj];
    }
  }

  for (int it = 0; it < 16; it++) {
    const int buf = it & 1, nbuf = buf ^ 1;
    const bool more = (it + 1 < 16);
    uint4 pk;
    if (more) {
      const int m0 = (it + 1) * 32;
#pragma unroll
      for (int j = 0; j < 4; j++) {
        int op = tid + 256 * j;
        int row = op >> 5, seg = op & 31;
        cp16(&sB[nbuf][row][seg * 8],
             g_xraw + (size_t)(b * NM + m0 + row) * ND + d0 + seg * 8);
      }
      if (tid < 128)
        pk = *reinterpret_cast<const uint4*>(
            &g_sap[(size_t)(b * NM + m0 + arow) * NK + aseg * 8]);
    }
    cp_commit();
    cp_wait1();
    __syncthreads();

    // ---- mma on stage it ----
#pragma unroll
    for (int ks = 0; ks < 2; ks++) {
      const int k0 = ks * 16;
      unsigned a0 = *reinterpret_cast<const unsigned*>(&sA[buf][16*mt + g    ][k0 + 2*q]);
      unsigned a1 = *reinterpret_cast<const unsigned*>(&sA[buf][16*mt + g + 8][k0 + 2*q]);
      unsigned a2 = *reinterpret_cast<const unsigned*>(&sA[buf][16*mt + g    ][k0 + 2*q + 8]);
      unsigned a3 = *reinterpret_cast<const unsigned*>(&sA[buf][16*mt + g + 8][k0 + 2*q + 8]);
#pragma unroll
      for (int nt = 0; nt < 8; nt++) {
        unsigned b0, b1;
        unsigned addr = (unsigned)__cvta_generic_to_shared(
            &sB[buf][k0 + (lane & 15)][nbase + 8 * nt]);
        asm volatile(
            "ldmatrix.sync.aligned.m8n8.x2.trans.shared.b16 {%0,%1}, [%2];\n"
            : "=r"(b0), "=r"(b1) : "r"(addr));
        mma_bf16(c[nt], a0, a1, a2, a3, b0, b1);
      }
    }

    if (more && tid < 128) {
      const __nv_bfloat16* hp = reinterpret_cast<const __nv_bfloat16*>(&pk);
#pragma unroll
      for (int jj = 0; jj < 8; jj++) sA[nbuf][aseg * 8 + jj][arow] = hp[jj];
    }
    __syncthreads();
  }

  // epilogue: vlad = C - S_k*centroid (kept in regs), partial sumsq
  const int rl = 16 * mt + g, rh = rl + 8;
  const float Sl = sS[rl], Sh = sS[rh];
  float sql = 0.f, sqh = 0.f;
#pragma unroll
  for (int nt = 0; nt < 8; nt++) {
    int col = d0 + nbase + 8 * nt + 2 * q;
    float2 cl = *reinterpret_cast<const float2*>(cent + (size_t)rl * ND + col);
    float2 ch = *reinterpret_cast<const float2*>(cent + (size_t)rh * ND + col);
    c[nt][0] -= Sl * cl.x;  c[nt][1] -= Sl * cl.y;
    c[nt][2] -= Sh * ch.x;  c[nt][3] -= Sh * ch.y;
    sql += c[nt][0]*c[nt][0] + c[nt][1]*c[nt][1];
    sqh += c[nt][2]*c[nt][2] + c[nt][3]*c[nt][3];
  }
  sql += __shfl_xor_sync(0xffffffffu, sql, 1);
  sql += __shfl_xor_sync(0xffffffffu, sql, 2);
  sqh += __shfl_xor_sync(0xffffffffu, sqh, 1);
  sqh += __shfl_xor_sync(0xffffffffu, sqh, 2);
  if (q == 0) { atomicAdd(&snsq[rl], sql); atomicAdd(&snsq[rh], sqh); }
  __syncthreads();

  // cross-CTA reduction: 8 CTAs per batch, all co-resident (single wave)
  if (tid < NK) atomicAdd(&g_nsq[b * NK + tid], snsq[tid]);
  __threadfence();
  __syncthreads();
  if (tid == 0) {
    __threadfence();
    atomicAdd(&g_cnt[b], 1);
    // bounded spin: never hangs even if the residency model is wrong
    for (long spin = 0; spin < 200000000L; spin++) {
      if (*reinterpret_cast<volatile int*>(&g_cnt[b]) >= 8) break;
      __nanosleep(100);
    }
  }
  __syncthreads();
  __threadfence();
  if (tid < NK) {
    float tot = atomicAdd(&g_nsq[b * NK + tid], 0.0f);
    sscl[tid] = rsqrtf(fmaxf(tot, 1e-24f) * 32.0f);  // incl final sqrt(K)
  }
  __syncthreads();

  // scale registers and write final output directly
  const float scl_l = sscl[rl], scl_h = sscl[rh];
  float* ob = out + (size_t)b * (NK * ND);
#pragma unroll
  for (int nt = 0; nt < 8; nt++) {
    int col = d0 + nbase + 8 * nt + 2 * q;
    float2 o0; o0.x = c[nt][0] * scl_l; o0.y = c[nt][1] * scl_l;
    float2 o1; o1.x = c[nt][2] * scl_h; o1.y = c[nt][3] * scl_h;
    *reinterpret_cast<float2*>(ob + (size_t)rl * ND + col) = o0;
    *reinterpret_cast<float2*>(ob + (size_t)rh * ND + col) = o1;
  }
}

extern "C" void kernel_launch(void* const* d_in, const int* in_sizes, int n_in,
                              void* d_out, int out_size) {
  const float* x    = (const float*)d_in[0];
  const float* Wm   = (const float*)d_in[1];
  const float* cent = (const float*)d_in[2];
  float* out = (float*)d_out;

  kz_kernel<<<8, 256>>>();
  ka_kernel<<<(NB * NM) / 64, 256>>>(x, Wm);
  kb2_kernel<<<NB * 8, 256>>>(cent, out);
}

// round 13
// speedup vs baseline: 1.1525x; 1.0134x over previous
#include <cuda_runtime.h>
#include <cuda_bf16.h>
#include <cstdint>

#define NB 64
#define NM 512
#define ND 2048
#define NK 32

// ---- scratch (device globals: allocation-free, zero-initialized) ----
__device__ __align__(256) __nv_bfloat16 g_xraw[(size_t)NB*NM*ND];  // bf16 x copy
__device__ __align__(256) __nv_bfloat16 g_sap[NB*NM*NK];           // sa * rnorm
__device__ float g_Spart[NB*8][NK];     // per-KA-block colsum parts (no atomics)
__device__ float g_nsqpart[NB*8][NK];   // per-kb2-CTA nsq parts
__device__ int   g_cnt[NB];             // monotonic ticket counters (never reset)

__device__ __forceinline__ void mma_bf16(float c[4],
    unsigned a0, unsigned a1, unsigned a2, unsigned a3,
    unsigned b0, unsigned b1) {
  asm volatile(
    "mma.sync.aligned.m16n8k16.row.col.f32.bf16.bf16.f32 "
    "{%0,%1,%2,%3}, {%4,%5,%6,%7}, {%8,%9}, {%0,%1,%2,%3};\n"
    : "+f"(c[0]), "+f"(c[1]), "+f"(c[2]), "+f"(c[3])
    : "r"(a0), "r"(a1), "r"(a2), "r"(a3), "r"(b0), "r"(b1));
}
__device__ __forceinline__ void cp16(void* dst, const void* src) {
  unsigned d = (unsigned)__cvta_generic_to_shared(dst);
  asm volatile("cp.async.cg.shared.global [%0], [%1], 16;\n" :: "r"(d), "l"(src));
}
__device__ __forceinline__ void cp_commit() { asm volatile("cp.async.commit_group;\n"); }
__device__ __forceinline__ void cp_wait1()  { asm volatile("cp.async.wait_group 1;\n"); }

// ================= KA: norm + logits + softmax (R2 core) ==================
#define KA_XS 72   // fp32 smem row stride (floats)
#define KA_WS 72   // bf16 smem row stride (halves)
#define KA_XBYTES (2*64*KA_XS*4)           // 36864
#define KA_WBYTES (2*32*KA_WS*2)           // 9216
__global__ __launch_bounds__(256) void ka_kernel(const float* __restrict__ x,
                                                 const float* __restrict__ Wm) {
  __shared__ __align__(16) char blob[KA_XBYTES + KA_WBYTES];
  float* xf = reinterpret_cast<float*>(blob);                 // [2][64][72]
  __nv_bfloat16* wb = reinterpret_cast<__nv_bfloat16*>(blob + KA_XBYTES); // [2][32][72]
  float (*slog)[36] = reinterpret_cast<float(*)[36]>(blob);   // alias (post-loop only)
  __shared__ float srn[64];

  const int tid = threadIdx.x, lane = tid & 31, w = tid >> 5;
  const int g = lane >> 2, q = lane & 3;
  const int r0 = blockIdx.x * 64;
  const int mt = w & 3, nbase = (w >> 2) * 16;

  float ssq = 0.f;
  float c[2][4];
#pragma unroll
  for (int i = 0; i < 2; i++) { c[i][0]=c[i][1]=c[i][2]=c[i][3]=0.f; }

  const int crow = tid >> 2, cseg = (tid & 3) * 16;   // convert-phase assignment
  const int wrw = tid >> 3, wcw = (tid & 7) * 8;      // W-load assignment

  // prologue: chunk 0
  {
#pragma unroll
    for (int j = 0; j < 4; j++) {
      int op = tid + 256 * j;
      int row = op >> 4, seg = op & 15;
      cp16(xf + row * KA_XS + seg * 4,
           x + (size_t)(r0 + row) * ND + seg * 4);
    }
    cp_commit();
    float4 wv0 = *reinterpret_cast<const float4*>(Wm + (size_t)wrw * ND + wcw);
    float4 wv1 = *reinterpret_cast<const float4*>(Wm + (size_t)wrw * ND + wcw + 4);
    __nv_bfloat162 h0 = __float22bfloat162_rn(make_float2(wv0.x, wv0.y));
    __nv_bfloat162 h1 = __float22bfloat162_rn(make_float2(wv0.z, wv0.w));
    __nv_bfloat162 h2 = __float22bfloat162_rn(make_float2(wv1.x, wv1.y));
    __nv_bfloat162 h3 = __float22bfloat162_rn(make_float2(wv1.z, wv1.w));
    uint4 pk;
    pk.x = *reinterpret_cast<unsigned*>(&h0); pk.y = *reinterpret_cast<unsigned*>(&h1);
    pk.z = *reinterpret_cast<unsigned*>(&h2); pk.w = *reinterpret_cast<unsigned*>(&h3);
    *reinterpret_cast<uint4*>(wb + wrw * KA_WS + wcw) = pk;
  }

  for (int it = 0; it < 32; it++) {
    const int buf = it & 1, nbuf = buf ^ 1;
    float4 wv0, wv1;
    const bool more = (it + 1 < 32);
    if (more) {
      const int c1 = (it + 1) * 64;
#pragma unroll
      for (int j = 0; j < 4; j++) {
        int op = tid + 256 * j;
        int row = op >> 4, seg = op & 15;
        cp16(xf + nbuf * (64 * KA_XS) + row * KA_XS + seg * 4,
             x + (size_t)(r0 + row) * ND + c1 + seg * 4);
      }
      wv0 = *reinterpret_cast<const float4*>(Wm + (size_t)wrw * ND + c1 + wcw);
      wv1 = *reinterpret_cast<const float4*>(Wm + (size_t)wrw * ND + c1 + wcw + 4);
    }
    cp_commit();
    cp_wait1();
    __syncthreads();

    const float* xb = xf + buf * (64 * KA_XS);
    const __nv_bfloat16* wbb = wb + buf * (32 * KA_WS);

    // convert + sumsq + bf16 global store
    {
      const float* src = xb + crow * KA_XS + cseg;
      float4 v0 = *reinterpret_cast<const float4*>(src);
      float4 v1 = *reinterpret_cast<const float4*>(src + 4);
      float4 v2 = *reinterpret_cast<const float4*>(src + 8);
      float4 v3 = *reinterpret_cast<const float4*>(src + 12);
      ssq += v0.x*v0.x + v0.y*v0.y + v0.z*v0.z + v0.w*v0.w
           + v1.x*v1.x + v1.y*v1.y + v1.z*v1.z + v1.w*v1.w
           + v2.x*v2.x + v2.y*v2.y + v2.z*v2.z + v2.w*v2.w
           + v3.x*v3.x + v3.y*v3.y + v3.z*v3.z + v3.w*v3.w;
      __nv_bfloat162 p0 = __float22bfloat162_rn(make_float2(v0.x, v0.y));
      __nv_bfloat162 p1 = __float22bfloat162_rn(make_float2(v0.z, v0.w));
      __nv_bfloat162 p2 = __float22bfloat162_rn(make_float2(v1.x, v1.y));
      __nv_bfloat162 p3 = __float22bfloat162_rn(make_float2(v1.z, v1.w));
      __nv_bfloat162 p4 = __float22bfloat162_rn(make_float2(v2.x, v2.y));
      __nv_bfloat162 p5 = __float22bfloat162_rn(make_float2(v2.z, v2.w));
      __nv_bfloat162 p6 = __float22bfloat162_rn(make_float2(v3.x, v3.y));
      __nv_bfloat162 p7 = __float22bfloat162_rn(make_float2(v3.z, v3.w));
      uint4 o0, o1;
      o0.x = *reinterpret_cast<unsigned*>(&p0); o0.y = *reinterpret_cast<unsigned*>(&p1);
      o0.z = *reinterpret_cast<unsigned*>(&p2); o0.w = *reinterpret_cast<unsigned*>(&p3);
      o1.x = *reinterpret_cast<unsigned*>(&p4); o1.y = *reinterpret_cast<unsigned*>(&p5);
      o1.z = *reinterpret_cast<unsigned*>(&p6); o1.w = *reinterpret_cast<unsigned*>(&p7);
      __nv_bfloat16* dst = g_xraw + (size_t)(r0 + crow) * ND + it * 64 + cseg;
      *reinterpret_cast<uint4*>(dst)     = o0;
      *reinterpret_cast<uint4*>(dst + 8) = o1;
    }

    // mma over this chunk: 4 k-steps of 16
#pragma unroll
    for (int ks = 0; ks < 4; ks++) {
      const int k0 = ks * 16;
      const int rl = 16 * mt + g;
      float2 pa = *reinterpret_cast<const float2*>(xb + rl * KA_XS + k0 + 2*q);
      float2 pb = *reinterpret_cast<const float2*>(xb + (rl+8) * KA_XS + k0 + 2*q);
      float2 pc = *reinterpret_cast<const float2*>(xb + rl * KA_XS + k0 + 2*q + 8);
      float2 pd = *reinterpret_cast<const float2*>(xb + (rl+8) * KA_XS + k0 + 2*q + 8);
      __nv_bfloat162 ha = __float22bfloat162_rn(pa);
      __nv_bfloat162 hb = __float22bfloat162_rn(pb);
      __nv_bfloat162 hc = __float22bfloat162_rn(pc);
      __nv_bfloat162 hd = __float22bfloat162_rn(pd);
      unsigned a0 = *reinterpret_cast<unsigned*>(&ha);
      unsigned a1 = *reinterpret_cast<unsigned*>(&hb);
      unsigned a2 = *reinterpret_cast<unsigned*>(&hc);
      unsigned a3 = *reinterpret_cast<unsigned*>(&hd);
#pragma unroll
      for (int nt = 0; nt < 2; nt++) {
        unsigned b0 = *reinterpret_cast<const unsigned*>(
            wbb + (nbase + 8*nt + g) * KA_WS + k0 + 2*q);
        unsigned b1 = *reinterpret_cast<const unsigned*>(
            wbb + (nbase + 8*nt + g) * KA_WS + k0 + 2*q + 8);
        mma_bf16(c[nt], a0, a1, a2, a3, b0, b1);
      }
    }

    if (more) {
      __nv_bfloat162 h0 = __float22bfloat162_rn(make_float2(wv0.x, wv0.y));
      __nv_bfloat162 h1 = __float22bfloat162_rn(make_float2(wv0.z, wv0.w));
      __nv_bfloat162 h2 = __float22bfloat162_rn(make_float2(wv1.x, wv1.y));
      __nv_bfloat162 h3 = __float22bfloat162_rn(make_float2(wv1.z, wv1.w));
      uint4 pk;
      pk.x = *reinterpret_cast<unsigned*>(&h0); pk.y = *reinterpret_cast<unsigned*>(&h1);
      pk.z = *reinterpret_cast<unsigned*>(&h2); pk.w = *reinterpret_cast<unsigned*>(&h3);
      *reinterpret_cast<uint4*>(wb + nbuf * (32 * KA_WS) + wrw * KA_WS + wcw) = pk;
    }
    __syncthreads();
  }

  // row norms
  ssq += __shfl_xor_sync(0xffffffffu, ssq, 1);
  ssq += __shfl_xor_sync(0xffffffffu, ssq, 2);
  if ((tid & 3) == 0) srn[crow] = rsqrtf(fmaxf(ssq, 1e-24f));

#pragma unroll
  for (int nt = 0; nt < 2; nt++) {
    slog[16*mt + g    ][nbase + 8*nt + 2*q]     = c[nt][0];
    slog[16*mt + g    ][nbase + 8*nt + 2*q + 1] = c[nt][1];
    slog[16*mt + g + 8][nbase + 8*nt + 2*q]     = c[nt][2];
    slog[16*mt + g + 8][nbase + 8*nt + 2*q + 1] = c[nt][3];
  }
  __syncthreads();

  if (tid < 64) {
    float rn = srn[tid];
    float l[NK];
    float mx = -1e30f;
#pragma unroll
    for (int k = 0; k < NK; k++) { l[k] = slog[tid][k] * rn; mx = fmaxf(mx, l[k]); }
    float s = 0.f;
#pragma unroll
    for (int k = 0; k < NK; k++) { l[k] = expf(l[k] - mx); s += l[k]; }
    float inv = 1.f / s;
#pragma unroll
    for (int k = 0; k < NK; k++) l[k] *= inv;
#pragma unroll
    for (int k = 0; k < NK; k += 8) {
      __nv_bfloat162 q0 = __float22bfloat162_rn(make_float2(l[k]*rn,   l[k+1]*rn));
      __nv_bfloat162 q1 = __float22bfloat162_rn(make_float2(l[k+2]*rn, l[k+3]*rn));
      __nv_bfloat162 q2 = __float22bfloat162_rn(make_float2(l[k+4]*rn, l[k+5]*rn));
      __nv_bfloat162 q3 = __float22bfloat162_rn(make_float2(l[k+6]*rn, l[k+7]*rn));
      uint4 pk;
      pk.x = *reinterpret_cast<unsigned*>(&q0); pk.y = *reinterpret_cast<unsigned*>(&q1);
      pk.z = *reinterpret_cast<unsigned*>(&q2); pk.w = *reinterpret_cast<unsigned*>(&q3);
      *reinterpret_cast<uint4*>(&g_sap[(size_t)(r0 + tid) * NK + k]) = pk;
    }
#pragma unroll
    for (int k = 0; k < NK; k++) slog[tid][k] = l[k];
  }
  __syncthreads();

  // colsum part: no atomics, no pre-zero — one disjoint slot per block
  if (tid < NK) {
    float s = 0.f;
#pragma unroll
    for (int r = 0; r < 64; r++) s += slog[r][tid];
    g_Spart[blockIdx.x][tid] = s;
  }
}

// ================= KB2: agg GEMM + fused normalize + coalesced output =====
// grid 512 (8 CTAs per batch), 39KB smem, launch_bounds(256,4) => single wave.
// Ticket barrier: monotonic counter, never reset, replay-safe by construction.
#define KB_SBS 264   // x tile stride (halves)
#define KB_SAS 40    // sa'^T tile stride (halves)
__global__ __launch_bounds__(256, 4) void kb2_kernel(const float* __restrict__ cent,
                                                     float* __restrict__ out) {
  __shared__ __align__(16) __nv_bfloat16 sB[2][32][KB_SBS];   // 33792 B
  __shared__ __align__(16) __nv_bfloat16 sA[2][NK][KB_SAS];
  __shared__ float sS[NK], snsq[NK], sscl[NK];

  const int tid = threadIdx.x, lane = tid & 31, w = tid >> 5;
  const int g = lane >> 2, q = lane & 3;
  const int b  = blockIdx.x >> 3;
  const int d0 = (blockIdx.x & 7) * 256;
  if (tid < NK) {
    float s = 0.f;
#pragma unroll
    for (int j = 0; j < 8; j++) s += g_Spart[b * 8 + j][tid];
    sS[tid] = s;
    snsq[tid] = 0.f;
  }

  const int mt = w & 1, nbase = (w >> 1) * 64;
  const int arow = tid >> 2, aseg = tid & 3;   // sa' load assignment (tid<128)
  float c[8][4];
#pragma unroll
  for (int i = 0; i < 8; i++) { c[i][0]=c[i][1]=c[i][2]=c[i][3]=0.f; }

  // prologue: stage 0
  {
#pragma unroll
    for (int j = 0; j < 4; j++) {
      int op = tid + 256 * j;
      int row = op >> 5, seg = op & 31;
      cp16(&sB[0][row][seg * 8],
           g_xraw + (size_t)(b * NM + row) * ND + d0 + seg * 8);
    }
    cp_commit();
    if (tid < 128) {
      uint4 pk = *reinterpret_cast<const uint4*>(
          &g_sap[(size_t)(b * NM + arow) * NK + aseg * 8]);
      const __nv_bfloat16* hp = reinterpret_cast<const __nv_bfloat16*>(&pk);
#pragma unroll
      for (int jj = 0; jj < 8; jj++) sA[0][aseg * 8 + jj][arow] = hp[jj];
    }
  }

  for (int it = 0; it < 16; it++) {
    const int buf = it & 1, nbuf = buf ^ 1;
    const bool more = (it + 1 < 16);
    uint4 pk;
    if (more) {
      const int m0 = (it + 1) * 32;
#pragma unroll
      for (int j = 0; j < 4; j++) {
        int op = tid + 256 * j;
        int row = op >> 5, seg = op & 31;
        cp16(&sB[nbuf][row][seg * 8],
             g_xraw + (size_t)(b * NM + m0 + row) * ND + d0 + seg * 8);
      }
      if (tid < 128)
        pk = *reinterpret_cast<const uint4*>(
            &g_sap[(size_t)(b * NM + m0 + arow) * NK + aseg * 8]);
    }
    cp_commit();
    cp_wait1();
    __syncthreads();

    // ---- mma on stage it ----
#pragma unroll
    for (int ks = 0; ks < 2; ks++) {
      const int k0 = ks * 16;
      unsigned a0 = *reinterpret_cast<const unsigned*>(&sA[buf][16*mt + g    ][k0 + 2*q]);
      unsigned a1 = *reinterpret_cast<const unsigned*>(&sA[buf][16*mt + g + 8][k0 + 2*q]);
      unsigned a2 = *reinterpret_cast<const unsigned*>(&sA[buf][16*mt + g    ][k0 + 2*q + 8]);
      unsigned a3 = *reinterpret_cast<const unsigned*>(&sA[buf][16*mt + g + 8][k0 + 2*q + 8]);
#pragma unroll
      for (int nt = 0; nt < 8; nt++) {
        unsigned b0, b1;
        unsigned addr = (unsigned)__cvta_generic_to_shared(
            &sB[buf][k0 + (lane & 15)][nbase + 8 * nt]);
        asm volatile(
            "ldmatrix.sync.aligned.m8n8.x2.trans.shared.b16 {%0,%1}, [%2];\n"
            : "=r"(b0), "=r"(b1) : "r"(addr));
        mma_bf16(c[nt], a0, a1, a2, a3, b0, b1);
      }
    }

    if (more && tid < 128) {
      const __nv_bfloat16* hp = reinterpret_cast<const __nv_bfloat16*>(&pk);
#pragma unroll
      for (int jj = 0; jj < 8; jj++) sA[nbuf][aseg * 8 + jj][arow] = hp[jj];
    }
    __syncthreads();
  }

  // epilogue: vlad = C - S_k*centroid (in regs), partial sumsq
  const int rl = 16 * mt + g, rh = rl + 8;
  const float Sl = sS[rl], Sh = sS[rh];
  float sql = 0.f, sqh = 0.f;
#pragma unroll
  for (int nt = 0; nt < 8; nt++) {
    int col = d0 + nbase + 8 * nt + 2 * q;
    float2 cl = *reinterpret_cast<const float2*>(cent + (size_t)rl * ND + col);
    float2 ch = *reinterpret_cast<const float2*>(cent + (size_t)rh * ND + col);
    c[nt][0] -= Sl * cl.x;  c[nt][1] -= Sl * cl.y;
    c[nt][2] -= Sh * ch.x;  c[nt][3] -= Sh * ch.y;
    sql += c[nt][0]*c[nt][0] + c[nt][1]*c[nt][1];
    sqh += c[nt][2]*c[nt][2] + c[nt][3]*c[nt][3];
  }
  sql += __shfl_xor_sync(0xffffffffu, sql, 1);
  sql += __shfl_xor_sync(0xffffffffu, sql, 2);
  sqh += __shfl_xor_sync(0xffffffffu, sqh, 1);
  sqh += __shfl_xor_sync(0xffffffffu, sqh, 2);
  if (q == 0) { atomicAdd(&snsq[rl], sql); atomicAdd(&snsq[rh], sqh); }
  __syncthreads();

  // publish this CTA's part, then ticket barrier (monotonic, reset-free)
  if (tid < NK) g_nsqpart[blockIdx.x][tid] = snsq[tid];
  __threadfence();
  __syncthreads();
  if (tid == 0) {
    int old = atomicAdd(&g_cnt[b], 1);
    int target = (old / 8) * 8 + 8;   // all 8 CTAs of this launch share target
    // bounded spin: degrades instead of hanging if residency model is wrong
    for (long spin = 0; spin < 200000000L; spin++) {
      if (*reinterpret_cast<volatile int*>(&g_cnt[b]) >= target) break;
      __nanosleep(100);
    }
  }
  __syncthreads();
  __threadfence();
  if (tid < NK) {
    float tot = 0.f;
#pragma unroll
    for (int j = 0; j < 8; j++) tot += g_nsqpart[b * 8 + j][tid];
    sscl[tid] = rsqrtf(fmaxf(tot, 1e-24f) * 32.0f);  // incl final sqrt(K)
  }
  __syncthreads();

  // stage scaled tile into sB (now dead) as fp32 [32][264], then coalesced STG
  float* fvac = reinterpret_cast<float*>(&sB[0][0][0]);
  {
    const float scl_l = sscl[rl], scl_h = sscl[rh];
#pragma unroll
    for (int nt = 0; nt < 8; nt++) {
      int cl_ = nbase + 8 * nt + 2 * q;
      float2 o0; o0.x = c[nt][0] * scl_l; o0.y = c[nt][1] * scl_l;
      float2 o1; o1.x = c[nt][2] * scl_h; o1.y = c[nt][3] * scl_h;
      *reinterpret_cast<float2*>(fvac + rl * 264 + cl_) = o0;
      *reinterpret_cast<float2*>(fvac + rh * 264 + cl_) = o1;
    }
  }
  __syncthreads();

  // conflict-free smem reads (lanes spread over all banks), coalesced stores
  float* ob = out + (size_t)b * (NK * ND) + d0;
  const int orow = tid >> 3, olane = (tid & 7) * 4;
#pragma unroll
  for (int i = 0; i < 8; i++) {
    float4 v = *reinterpret_cast<const float4*>(fvac + orow * 264 + olane + i * 32);
    *reinterpret_cast<float4*>(ob + (size_t)orow * ND + olane + i * 32) = v;
  }
}

extern "C" void kernel_launch(void* const* d_in, const int* in_sizes, int n_in,
                              void* d_out, int out_size) {
  const float* x    = (const float*)d_in[0];
  const float* Wm   = (const float*)d_in[1];
  const float* cent = (const float*)d_in[2];
  float* out = (float*)d_out;

  ka_kernel<<<(NB * NM) / 64, 256>>>(x, Wm);
  kb2_kernel<<<NB * 8, 256>>>(cent, out);
}